// round 2
// baseline (speedup 1.0000x reference)
#include <cuda_runtime.h>

// Performer / FAVOR+ non-causal attention, fp32 SIMT baseline with f32x2 packed FMA.
// Shapes: b=8,h=8,n=4096,d=64,m=256. Inputs: q,k,v [b,h,n,d] fp32; P [m,d] fp32.
// Output: [b,h,n,d] fp32.

#define NSEQ   4096
#define BH     64
#define NT     (BH*NSEQ)      // 262144 rows per tensor
#define MF     256            // feature dim m
#define DD     64             // head dim d
#define SPLIT  8
#define RATIO  0.0625f        // m^-0.5
#define REPS   6.25e-6f       // ratio * eps (eps=1e-4)
#define DN     0.35355339059327373f  // d^-0.25 = 2^-1.5

// ---------------- scratch (static device globals; no allocation) ----------------
__device__ float g_qp [(size_t)NT * MF];          // q' fully transformed (268 MB)
__device__ float g_kE [(size_t)NT * MF];          // exp(kdash - diag)    (268 MB)
__device__ float g_pctx[(size_t)SPLIT * BH * MF * DD];  // partial contexts
__device__ float g_pks [(size_t)SPLIT * BH * MF];       // partial k_sums
__device__ float g_ctx [(size_t)BH * MF * DD];
__device__ float g_ksum[(size_t)BH * MF];
__device__ unsigned g_kmax_u;                     // global max of k-dash (ordered uint)

// ---------------- helpers ----------------
typedef unsigned long long ull;

__device__ __forceinline__ void fma2(ull& c, ull a, ull b) {
    asm("fma.rn.f32x2 %0, %1, %2, %0;" : "+l"(c) : "l"(a), "l"(b));
}
__device__ __forceinline__ ull packdup(float x) {
    ull r; unsigned u = __float_as_uint(x);
    asm("mov.b64 %0, {%1, %1};" : "=l"(r) : "r"(u));
    return r;
}
__device__ __forceinline__ void unpack2(ull v, float& lo, float& hi) {
    unsigned a, b;
    asm("mov.b64 {%0, %1}, %2;" : "=r"(a), "=r"(b) : "l"(v));
    lo = __uint_as_float(a); hi = __uint_as_float(b);
}
__device__ __forceinline__ unsigned enc_f(float f) {
    unsigned u = __float_as_uint(f);
    return (u & 0x80000000u) ? ~u : (u | 0x80000000u);
}
__device__ __forceinline__ float dec_f(unsigned e) {
    return __uint_as_float((e & 0x80000000u) ? (e ^ 0x80000000u) : ~e);
}

// ---------------- K0: init global max ----------------
__global__ void k_init() {
    if (threadIdx.x == 0 && blockIdx.x == 0) g_kmax_u = 0u;
}

// ---------------- K1: projection GEMM + transform ----------------
// grid (4096, 2): y=0 -> q (store q'), y=1 -> k (store E, reduce global max)
// block 256 threads; tile = 64 rows x 256 cols, K=64 in one shot.
// smem: Pt[64][260] (dn*P transposed), As[64][68], diag[64], red[256]
#define K1_SMEM ((64*260 + 64*68 + 64 + 256) * 4)

__global__ void __launch_bounds__(256, 2)
k_proj(const float* __restrict__ q, const float* __restrict__ k,
       const float* __restrict__ P) {
    extern __shared__ float sm[];
    float* Pt     = sm;                    // 64*260
    float* As     = sm + 64*260;           // 64*68
    float* diag_s = As + 64*68;            // 64
    float* red_s  = diag_s + 64;           // 256

    const int t  = threadIdx.x;
    const int tx = t & 15, ty = t >> 4;
    const int is_k = blockIdx.y;
    const int rowbase = blockIdx.x * 64;
    const float* __restrict__ X = is_k ? k : q;
    float* __restrict__ Out = is_k ? g_kE : g_qp;

    // Load P transposed, pre-scaled by dn: Pt[d][m] = dn*P[m][d]
    const float4* P4 = (const float4*)P;
    #pragma unroll
    for (int it = 0; it < 16; ++it) {
        int vv = it * 256 + t;
        float4 p = P4[vv];
        int m = vv >> 4, d4 = (vv & 15) * 4;
        Pt[(d4+0)*260 + m] = DN * p.x;
        Pt[(d4+1)*260 + m] = DN * p.y;
        Pt[(d4+2)*260 + m] = DN * p.z;
        Pt[(d4+3)*260 + m] = DN * p.w;
    }
    // Load A tile (raw, unscaled -> diag comes for free)
    const float4* X4 = (const float4*)(X + (size_t)rowbase * DD);
    #pragma unroll
    for (int it = 0; it < 4; ++it) {
        int vv = it * 256 + t;
        *(float4*)(As + (vv >> 4) * 68 + (vv & 15) * 4) = X4[vv];
    }
    __syncthreads();

    if (t < 64) {
        float s = 0.f;
        #pragma unroll
        for (int kk = 0; kk < 64; ++kk) { float a = As[t*68 + kk]; s += a * a; }
        diag_s[t] = 0.0625f * s;    // 0.5 * dn^2 * ||x||^2
    }
    __syncthreads();

    // Main GEMM: 4 rows x 16 cols per thread, cols = 4*tx + 64*J + {0..3}
    ull acc[4][8] = {};
    #pragma unroll 8
    for (int kk = 0; kk < 64; ++kk) {
        float a0 = As[(ty*4+0)*68 + kk];
        float a1 = As[(ty*4+1)*68 + kk];
        float a2 = As[(ty*4+2)*68 + kk];
        float a3 = As[(ty*4+3)*68 + kk];
        ull d0 = packdup(a0), d1 = packdup(a1), d2 = packdup(a2), d3 = packdup(a3);
        const float* pr = Pt + kk * 260 + 4 * tx;
        #pragma unroll
        for (int J = 0; J < 4; ++J) {
            ulonglong2 bb = *(const ulonglong2*)(pr + 64 * J);
            fma2(acc[0][2*J], d0, bb.x); fma2(acc[0][2*J+1], d0, bb.y);
            fma2(acc[1][2*J], d1, bb.x); fma2(acc[1][2*J+1], d1, bb.y);
            fma2(acc[2][2*J], d2, bb.x); fma2(acc[2][2*J+1], d2, bb.y);
            fma2(acc[3][2*J], d3, bb.x); fma2(acc[3][2*J+1], d3, bb.y);
        }
    }

    // Per-row max of dash over this thread's 16 cols
    float rm[4];
    #pragma unroll
    for (int i = 0; i < 4; ++i) {
        float mx = -1e30f;
        #pragma unroll
        for (int j = 0; j < 8; ++j) {
            float lo, hi; unpack2(acc[i][j], lo, hi);
            mx = fmaxf(mx, fmaxf(lo, hi));
        }
        rm[i] = mx;
    }

    if (!is_k) {
        // row max across the 16 tx lanes sharing these rows
        #pragma unroll
        for (int i = 0; i < 4; ++i)
            #pragma unroll
            for (int o = 8; o >= 1; o >>= 1)
                rm[i] = fmaxf(rm[i], __shfl_xor_sync(0xffffffffu, rm[i], o));
        #pragma unroll
        for (int i = 0; i < 4; ++i) {
            float c = diag_s[ty*4 + i] + rm[i];
            float4* ob = (float4*)(Out + (size_t)(rowbase + ty*4 + i) * MF + 4*tx);
            #pragma unroll
            for (int J = 0; J < 4; ++J) {
                float l0, h0, l1, h1;
                unpack2(acc[i][2*J],   l0, h0);
                unpack2(acc[i][2*J+1], l1, h1);
                float4 o;
                o.x = fmaf(RATIO, __expf(l0 - c), REPS);
                o.y = fmaf(RATIO, __expf(h0 - c), REPS);
                o.z = fmaf(RATIO, __expf(l1 - c), REPS);
                o.w = fmaf(RATIO, __expf(h1 - c), REPS);
                ob[16 * J] = o;
            }
        }
    } else {
        #pragma unroll
        for (int i = 0; i < 4; ++i) {
            float c = diag_s[ty*4 + i];
            float4* ob = (float4*)(Out + (size_t)(rowbase + ty*4 + i) * MF + 4*tx);
            #pragma unroll
            for (int J = 0; J < 4; ++J) {
                float l0, h0, l1, h1;
                unpack2(acc[i][2*J],   l0, h0);
                unpack2(acc[i][2*J+1], l1, h1);
                float4 o;
                o.x = __expf(l0 - c);
                o.y = __expf(h0 - c);
                o.z = __expf(l1 - c);
                o.w = __expf(h1 - c);
                ob[16 * J] = o;
            }
        }
        // block-wide max of dash -> global atomic
        float bm = fmaxf(fmaxf(rm[0], rm[1]), fmaxf(rm[2], rm[3]));
        red_s[t] = bm;
        __syncthreads();
        for (int s = 128; s > 0; s >>= 1) {
            if (t < s) red_s[t] = fmaxf(red_s[t], red_s[t + s]);
            __syncthreads();
        }
        if (t == 0) atomicMax(&g_kmax_u, enc_f(red_s[0]));
    }
}

// ---------------- K2: k' accumulation (ksum + context partials) ----------------
// grid (SPLIT, BH), block 256. Thread t owns feature m=t; acc over e in f32x2 pairs.
__global__ void __launch_bounds__(256, 2)
k_ctx(const float* __restrict__ v) {
    __shared__ __align__(16) float vbuf[8][64];
    const int t = threadIdx.x;
    const int bh = blockIdx.y, s = blockIdx.x;
    const int n0 = s * (NSEQ / SPLIT);

    const float c1 = RATIO * __expf(-dec_f(g_kmax_u));
    ull acc[32] = {};
    float ks = 0.f;
    const float* __restrict__ Eb = g_kE + (size_t)(bh * NSEQ + n0) * MF;
    const float* __restrict__ vb = v   + (size_t)(bh * NSEQ + n0) * DD;

    for (int nc = 0; nc < NSEQ / SPLIT; nc += 8) {
        #pragma unroll
        for (int u = 0; u < 2; ++u) {
            int idx = u * 256 + t;
            ((float*)vbuf)[idx] = vb[nc * 64 + idx];
        }
        __syncthreads();
        #pragma unroll
        for (int nn = 0; nn < 8; ++nn) {
            float E  = Eb[(size_t)(nc + nn) * MF + t];
            float kp = fmaf(c1, E, REPS);
            ks += kp;
            ull kd = packdup(kp);
            const ulonglong2* vv = (const ulonglong2*)vbuf[nn];
            #pragma unroll
            for (int qd = 0; qd < 16; ++qd) {
                ulonglong2 b = vv[qd];
                fma2(acc[2*qd],     kd, b.x);
                fma2(acc[2*qd + 1], kd, b.y);
            }
        }
        __syncthreads();
    }
    const int pidx = s * BH + bh;
    g_pks[(size_t)pidx * MF + t] = ks;
    float* cb = g_pctx + (size_t)pidx * (MF * DD) + t * DD;
    #pragma unroll
    for (int p = 0; p < 32; ++p) {
        float lo, hi; unpack2(acc[p], lo, hi);
        cb[2*p] = lo; cb[2*p + 1] = hi;
    }
}

// ---------------- K2b: deterministic partial reduction ----------------
__global__ void k_red() {
    const int bx = blockIdx.x, t = threadIdx.x;
    if (bx < 4096) {
        size_t i = (size_t)bx * 256 + t;          // < 1048576
        float s = 0.f;
        #pragma unroll
        for (int p = 0; p < SPLIT; ++p) s += g_pctx[(size_t)p * 1048576 + i];
        g_ctx[i] = s;
    } else {
        size_t j = (size_t)(bx - 4096) * 256 + t; // < 16384
        float s = 0.f;
        #pragma unroll
        for (int p = 0; p < SPLIT; ++p) s += g_pks[(size_t)p * 16384 + j];
        g_ksum[j] = s;
    }
}

// ---------------- K3: out = (q' @ context) * D^-1 ----------------
// grid 4096 blocks (64 rows each), 256 threads, 4 threads per row (e split by 16).
// smem: ctx[256][64] + qps[64][257] + ksum[256]
#define K3_SMEM ((16384 + 64*257 + 256) * 4)

__global__ void __launch_bounds__(256)
k_out(float* __restrict__ out) {
    extern __shared__ float sm[];
    float* ctx_s = sm;                 // 16384
    float* qps   = sm + 16384;         // 64*257
    float* ks_s  = qps + 64*257;       // 256

    const int t  = threadIdx.x;
    const int R0 = blockIdx.x * 64;
    const int bh = R0 >> 12;

    ks_s[t] = g_ksum[(size_t)bh * MF + t];
    const float4* c4 = (const float4*)(g_ctx + (size_t)bh * (MF * DD));
    #pragma unroll
    for (int it = 0; it < 16; ++it)
        ((float4*)ctx_s)[it * 256 + t] = c4[it * 256 + t];
    const float4* q4 = (const float4*)(g_qp + (size_t)R0 * MF);
    #pragma unroll
    for (int it = 0; it < 16; ++it) {
        int vv = it * 256 + t;
        float4 p = q4[vv];
        int r = vv >> 6, c = (vv & 63) * 4;
        qps[r*257 + c + 0] = p.x;
        qps[r*257 + c + 1] = p.y;
        qps[r*257 + c + 2] = p.z;
        qps[r*257 + c + 3] = p.w;
    }
    __syncthreads();

    const int r = t >> 2, g = t & 3;
    const float* qrow = qps + r * 257;

    // D = sum_m q'[m] * ksum[m]  (split over 4 lanes, shfl-combine)
    float dsum = 0.f;
    #pragma unroll 8
    for (int mm = g * 64; mm < g * 64 + 64; ++mm) dsum += qrow[mm] * ks_s[mm];
    dsum += __shfl_xor_sync(0xffffffffu, dsum, 1);
    dsum += __shfl_xor_sync(0xffffffffu, dsum, 2);
    const float invd = 1.0f / dsum;

    ull acc[8] = {};
    const float* cb0 = ctx_s + g * 16;
    #pragma unroll 4
    for (int mm = 0; mm < 256; ++mm) {
        ull qd = packdup(qrow[mm]);
        const ulonglong2* cc = (const ulonglong2*)(cb0 + mm * 64);
        #pragma unroll
        for (int p2 = 0; p2 < 4; ++p2) {
            ulonglong2 b = cc[p2];
            fma2(acc[2*p2],     qd, b.x);
            fma2(acc[2*p2 + 1], qd, b.y);
        }
    }
    float2* ob = (float2*)(out + (size_t)(R0 + r) * DD + g * 16);
    #pragma unroll
    for (int p = 0; p < 8; ++p) {
        float lo, hi; unpack2(acc[p], lo, hi);
        ob[p] = make_float2(lo * invd, hi * invd);
    }
}

// ---------------- launch ----------------
extern "C" void kernel_launch(void* const* d_in, const int* in_sizes, int n_in,
                              void* d_out, int out_size) {
    const float* q = (const float*)d_in[0];
    const float* k = (const float*)d_in[1];
    const float* v = (const float*)d_in[2];
    const float* P = (const float*)d_in[3];
    float* out = (float*)d_out;

    cudaFuncSetAttribute(k_proj, cudaFuncAttributeMaxDynamicSharedMemorySize, K1_SMEM);
    cudaFuncSetAttribute(k_out,  cudaFuncAttributeMaxDynamicSharedMemorySize, K3_SMEM);

    k_init<<<1, 32>>>();
    dim3 g1(NT / 64, 2);
    k_proj<<<g1, 256, K1_SMEM>>>(q, k, P);
    dim3 g2(SPLIT, BH);
    k_ctx<<<g2, 256>>>(v);
    k_red<<<4096 + 64, 256>>>();
    k_out<<<NT / 64, 256, K3_SMEM>>>(out);
}

// round 5
// speedup vs baseline: 1.1174x; 1.1174x over previous
#include <cuda_runtime.h>

// Performer / FAVOR+ non-causal attention.
// K1: tf32 mma.sync projection+transform; K2/K3: fp32 SIMT; deterministic split-K.
// Shapes: b=8,h=8,n=4096,d=64,m=256. q,k,v [b,h,n,d] fp32; P [m,d] fp32. Out [b,h,n,d] fp32.

#define NSEQ   4096
#define BH     64
#define NT     (BH*NSEQ)      // 262144 rows
#define MF     256
#define DD     64
#define SPLIT  8
#define RATIO  0.0625f        // m^-0.5
#define REPS   6.25e-6f       // ratio * eps
#define DN     0.35355339059327373f  // d^-0.25

// ---------------- scratch ----------------
__device__ float g_qp [(size_t)NT * MF];
__device__ float g_kE [(size_t)NT * MF];
__device__ float g_pctx[(size_t)SPLIT * BH * MF * DD];
__device__ float g_pks [(size_t)SPLIT * BH * MF];
__device__ float g_ctx [(size_t)BH * MF * DD];
__device__ float g_ksum[(size_t)BH * MF];
__device__ unsigned g_kmax_u = 0u;   // ordered-uint max of k-dash; atomicMax is replay-idempotent

// ---------------- helpers ----------------
__device__ __forceinline__ unsigned enc_f(float f) {
    unsigned u = __float_as_uint(f);
    return (u & 0x80000000u) ? ~u : (u | 0x80000000u);
}
__device__ __forceinline__ float dec_f(unsigned e) {
    return __uint_as_float((e & 0x80000000u) ? (e ^ 0x80000000u) : ~e);
}
__device__ __forceinline__ unsigned tf32b(float f) {
    unsigned r; asm("cvt.rna.tf32.f32 %0, %1;" : "=r"(r) : "f"(f)); return r;
}
__device__ __forceinline__ void mma8(float* c, const unsigned* a, unsigned b0, unsigned b1) {
    asm volatile(
        "mma.sync.aligned.m16n8k8.row.col.f32.tf32.tf32.f32 "
        "{%0,%1,%2,%3},{%4,%5,%6,%7},{%8,%9},{%0,%1,%2,%3};"
        : "+f"(c[0]), "+f"(c[1]), "+f"(c[2]), "+f"(c[3])
        : "r"(a[0]), "r"(a[1]), "r"(a[2]), "r"(a[3]), "r"(b0), "r"(b1));
}

// ---------------- K1: tf32 tensor-core projection + transform ----------------
// grid (4096, 2): y=0 -> q (store q'), y=1 -> k (store E + global max).
// 256 threads = 8 warps; GEMM tile M=64 rows x N=256 feats, K=64.
// Warp grid 2(M) x 4(N); warp tile 32x64; per warp: mt{0,1} x nt{0..7} m16n8 C tiles.
// smem: Ps[256][68] tf32(DN*P), Xs[64][68] tf32(x), diag[64], rowred[64][4], red[256]
#define K1_SMEM ((256*68 + 64*68 + 64 + 256 + 256) * 4)

__global__ void __launch_bounds__(256, 1)
k_proj(const float* __restrict__ q, const float* __restrict__ k,
       const float* __restrict__ P) {
    extern __shared__ unsigned smu[];
    unsigned* Ps    = smu;                       // 256*68
    unsigned* Xs    = smu + 256*68;              // 64*68
    float* diag_s   = (float*)(smu + 256*68 + 64*68);  // 64
    float* rowred   = diag_s + 64;               // 64*4
    float* red_s    = rowred + 256;              // 256

    const int t  = threadIdx.x;
    const int is_k = blockIdx.y;
    const int rowbase = blockIdx.x * 64;
    const float* __restrict__ X = is_k ? k : q;
    float* __restrict__ Out = is_k ? g_kE : g_qp;

    // Stage P as tf32(DN*P): Ps[m][d], stride 68
    const float4* P4 = (const float4*)P;
    #pragma unroll
    for (int it = 0; it < 16; ++it) {
        int vv = it * 256 + t;
        float4 p = P4[vv];
        int m = vv >> 4, d4 = (vv & 15) * 4;
        Ps[m*68 + d4 + 0] = tf32b(DN * p.x);
        Ps[m*68 + d4 + 1] = tf32b(DN * p.y);
        Ps[m*68 + d4 + 2] = tf32b(DN * p.z);
        Ps[m*68 + d4 + 3] = tf32b(DN * p.w);
    }
    // Stage X tile as tf32: Xs[r][d], stride 68
    const float4* X4 = (const float4*)(X + (size_t)rowbase * DD);
    #pragma unroll
    for (int it = 0; it < 4; ++it) {
        int vv = it * 256 + t;
        float4 x = X4[vv];
        int r = vv >> 4, d4 = (vv & 15) * 4;
        Xs[r*68 + d4 + 0] = tf32b(x.x);
        Xs[r*68 + d4 + 1] = tf32b(x.y);
        Xs[r*68 + d4 + 2] = tf32b(x.z);
        Xs[r*68 + d4 + 3] = tf32b(x.w);
    }
    __syncthreads();

    // diag in FULL fp32 precision from global (L1/L2 hot)
    if (t < 64) {
        const float4* xr = (const float4*)(X + (size_t)(rowbase + t) * DD);
        float s = 0.f;
        #pragma unroll
        for (int d4 = 0; d4 < 16; ++d4) {
            float4 x = xr[d4];
            s += x.x*x.x + x.y*x.y + x.z*x.z + x.w*x.w;
        }
        diag_s[t] = 0.0625f * s;   // 0.5 * dn^2 * ||x||^2
    }

    const int lane = t & 31, wid = t >> 5;
    const int wm = wid >> 2, wn = wid & 3;
    const int gr = lane >> 2, tg = lane & 3;

    float c[2][8][4];
    #pragma unroll
    for (int mt = 0; mt < 2; ++mt)
        #pragma unroll
        for (int nt = 0; nt < 8; ++nt)
            #pragma unroll
            for (int j = 0; j < 4; ++j) c[mt][nt][j] = 0.f;

    #pragma unroll
    for (int ks = 0; ks < 8; ++ks) {
        const int k0 = ks * 8;
        unsigned a[2][4];
        #pragma unroll
        for (int mt = 0; mt < 2; ++mt) {
            const int r0 = wm*32 + mt*16 + gr;
            a[mt][0] = Xs[r0*68       + k0 + tg];
            a[mt][1] = Xs[(r0+8)*68   + k0 + tg];
            a[mt][2] = Xs[r0*68       + k0 + tg + 4];
            a[mt][3] = Xs[(r0+8)*68   + k0 + tg + 4];
        }
        #pragma unroll
        for (int nt = 0; nt < 8; ++nt) {
            const int n0 = wn*64 + nt*8 + gr;
            unsigned b0 = Ps[n0*68 + k0 + tg];
            unsigned b1 = Ps[n0*68 + k0 + tg + 4];
            mma8(c[0][nt], a[0], b0, b1);
            mma8(c[1][nt], a[1], b0, b1);
        }
    }
    __syncthreads();   // diag visible; mma done

    if (!is_k) {
        // per-row max of dash: thread-local over nt, shfl over tg lanes, smem over wn warps
        #pragma unroll
        for (int mt = 0; mt < 2; ++mt) {
            float m0 = -1e30f, m1 = -1e30f;
            #pragma unroll
            for (int nt = 0; nt < 8; ++nt) {
                m0 = fmaxf(m0, fmaxf(c[mt][nt][0], c[mt][nt][1]));
                m1 = fmaxf(m1, fmaxf(c[mt][nt][2], c[mt][nt][3]));
            }
            m0 = fmaxf(m0, __shfl_xor_sync(0xffffffffu, m0, 1));
            m0 = fmaxf(m0, __shfl_xor_sync(0xffffffffu, m0, 2));
            m1 = fmaxf(m1, __shfl_xor_sync(0xffffffffu, m1, 1));
            m1 = fmaxf(m1, __shfl_xor_sync(0xffffffffu, m1, 2));
            if (tg == 0) {
                rowred[(wm*32 + mt*16 + gr)     * 4 + wn] = m0;
                rowred[(wm*32 + mt*16 + gr + 8) * 4 + wn] = m1;
            }
        }
        __syncthreads();
        #pragma unroll
        for (int mt = 0; mt < 2; ++mt) {
            #pragma unroll
            for (int ro = 0; ro < 2; ++ro) {
                const int row = wm*32 + mt*16 + gr + ro*8;
                const float rmax = fmaxf(fmaxf(rowred[row*4+0], rowred[row*4+1]),
                                         fmaxf(rowred[row*4+2], rowred[row*4+3]));
                const float cc = diag_s[row] + rmax;
                float* ob = Out + (size_t)(rowbase + row) * MF + wn*64 + 2*tg;
                #pragma unroll
                for (int nt = 0; nt < 8; ++nt) {
                    float2 o;
                    o.x = fmaf(RATIO, __expf(c[mt][nt][2*ro+0] - cc), REPS);
                    o.y = fmaf(RATIO, __expf(c[mt][nt][2*ro+1] - cc), REPS);
                    *(float2*)(ob + nt*8) = o;
                }
            }
        }
    } else {
        float bm = -1e30f;
        #pragma unroll
        for (int mt = 0; mt < 2; ++mt) {
            #pragma unroll
            for (int ro = 0; ro < 2; ++ro) {
                const int row = wm*32 + mt*16 + gr + ro*8;
                const float cc = diag_s[row];
                float* ob = Out + (size_t)(rowbase + row) * MF + wn*64 + 2*tg;
                #pragma unroll
                for (int nt = 0; nt < 8; ++nt) {
                    float v0 = c[mt][nt][2*ro+0], v1 = c[mt][nt][2*ro+1];
                    bm = fmaxf(bm, fmaxf(v0, v1));
                    float2 o;
                    o.x = __expf(v0 - cc);
                    o.y = __expf(v1 - cc);
                    *(float2*)(ob + nt*8) = o;
                }
            }
        }
        red_s[t] = bm;
        __syncthreads();
        for (int s = 128; s > 0; s >>= 1) {
            if (t < s) red_s[t] = fmaxf(red_s[t], red_s[t + s]);
            __syncthreads();
        }
        if (t == 0) atomicMax(&g_kmax_u, enc_f(red_s[0]));
    }
}

// ---------------- K2: context partials  ctx_part = sum_n k'_n (x) v_n ----------------
// grid (SPLIT, BH), 256 threads; thread t owns feature m=t. Plain fp32 FMA.
__global__ void __launch_bounds__(256, 2)
k_ctx(const float* __restrict__ v) {
    __shared__ __align__(16) float4 vbuf[8][16];
    const int t = threadIdx.x;
    const int bh = blockIdx.y, s = blockIdx.x;
    const int n0 = s * (NSEQ / SPLIT);

    const float c1 = RATIO * __expf(-dec_f(g_kmax_u));
    float acc[64];
    #pragma unroll
    for (int i = 0; i < 64; ++i) acc[i] = 0.f;
    float ks = 0.f;
    const float* __restrict__ Eb = g_kE + (size_t)(bh * NSEQ + n0) * MF;
    const float4* __restrict__ vb4 = (const float4*)(v + (size_t)(bh * NSEQ + n0) * DD);

    for (int nc = 0; nc < NSEQ / SPLIT; nc += 8) {
        if (t < 128) ((float4*)vbuf)[t] = vb4[nc * 16 + t];
        __syncthreads();
        #pragma unroll
        for (int nn = 0; nn < 8; ++nn) {
            float E  = Eb[(size_t)(nc + nn) * MF + t];
            float kp = fmaf(c1, E, REPS);
            ks += kp;
            const float4* vv = vbuf[nn];
            #pragma unroll
            for (int qd = 0; qd < 16; ++qd) {
                float4 b = vv[qd];
                acc[4*qd+0] = fmaf(kp, b.x, acc[4*qd+0]);
                acc[4*qd+1] = fmaf(kp, b.y, acc[4*qd+1]);
                acc[4*qd+2] = fmaf(kp, b.z, acc[4*qd+2]);
                acc[4*qd+3] = fmaf(kp, b.w, acc[4*qd+3]);
            }
        }
        __syncthreads();
    }
    const int pidx = s * BH + bh;
    g_pks[(size_t)pidx * MF + t] = ks;
    float4* cb = (float4*)(g_pctx + (size_t)pidx * (MF * DD) + t * DD);
    #pragma unroll
    for (int p = 0; p < 16; ++p)
        cb[p] = make_float4(acc[4*p], acc[4*p+1], acc[4*p+2], acc[4*p+3]);
}

// ---------------- K2b: deterministic partial reduction ----------------
__global__ void k_red() {
    const int bx = blockIdx.x, t = threadIdx.x;
    if (bx < 4096) {
        size_t i = (size_t)bx * 256 + t;
        float s = 0.f;
        #pragma unroll
        for (int p = 0; p < SPLIT; ++p) s += g_pctx[(size_t)p * 1048576 + i];
        g_ctx[i] = s;
    } else {
        size_t j = (size_t)(bx - 4096) * 256 + t;
        float s = 0.f;
        #pragma unroll
        for (int p = 0; p < SPLIT; ++p) s += g_pks[(size_t)p * 16384 + j];
        g_ksum[j] = s;
    }
}

// ---------------- K3: out = (q' @ context) * D^-1 ----------------
#define K3_SMEM ((16384 + 64*257 + 256) * 4)

__global__ void __launch_bounds__(256)
k_out(float* __restrict__ out) {
    extern __shared__ float sm[];
    float* ctx_s = sm;                 // 256*64
    float* qps   = sm + 16384;         // 64*257
    float* ks_s  = qps + 64*257;       // 256

    const int t  = threadIdx.x;
    const int R0 = blockIdx.x * 64;
    const int bh = R0 >> 12;

    ks_s[t] = g_ksum[(size_t)bh * MF + t];
    const float4* c4 = (const float4*)(g_ctx + (size_t)bh * (MF * DD));
    #pragma unroll
    for (int it = 0; it < 16; ++it)
        ((float4*)ctx_s)[it * 256 + t] = c4[it * 256 + t];
    const float4* q4 = (const float4*)(g_qp + (size_t)R0 * MF);
    #pragma unroll
    for (int it = 0; it < 16; ++it) {
        int vv = it * 256 + t;
        float4 p = q4[vv];
        int r = vv >> 6, c = (vv & 63) * 4;
        qps[r*257 + c + 0] = p.x;
        qps[r*257 + c + 1] = p.y;
        qps[r*257 + c + 2] = p.z;
        qps[r*257 + c + 3] = p.w;
    }
    __syncthreads();

    const int r = t >> 2, g = t & 3;
    const float* qrow = qps + r * 257;

    float dsum = 0.f;
    #pragma unroll 8
    for (int mm = g * 64; mm < g * 64 + 64; ++mm) dsum += qrow[mm] * ks_s[mm];
    dsum += __shfl_xor_sync(0xffffffffu, dsum, 1);
    dsum += __shfl_xor_sync(0xffffffffu, dsum, 2);
    const float invd = 1.0f / dsum;

    float acc[16];
    #pragma unroll
    for (int i = 0; i < 16; ++i) acc[i] = 0.f;
    const float4* cb0 = (const float4*)(ctx_s + g * 16);
    #pragma unroll 4
    for (int mm = 0; mm < 256; ++mm) {
        float qv = qrow[mm];
        const float4* cc = cb0 + mm * 16;
        #pragma unroll
        for (int p2 = 0; p2 < 4; ++p2) {
            float4 b = cc[p2];
            acc[4*p2+0] = fmaf(qv, b.x, acc[4*p2+0]);
            acc[4*p2+1] = fmaf(qv, b.y, acc[4*p2+1]);
            acc[4*p2+2] = fmaf(qv, b.z, acc[4*p2+2]);
            acc[4*p2+3] = fmaf(qv, b.w, acc[4*p2+3]);
        }
    }
    float4* ob = (float4*)(out + (size_t)(R0 + r) * DD + g * 16);
    #pragma unroll
    for (int p = 0; p < 4; ++p)
        ob[p] = make_float4(acc[4*p]*invd, acc[4*p+1]*invd, acc[4*p+2]*invd, acc[4*p+3]*invd);
}

// ---------------- launch ----------------
extern "C" void kernel_launch(void* const* d_in, const int* in_sizes, int n_in,
                              void* d_out, int out_size) {
    const float* q = (const float*)d_in[0];
    const float* k = (const float*)d_in[1];
    const float* v = (const float*)d_in[2];
    const float* P = (const float*)d_in[3];
    float* out = (float*)d_out;

    cudaFuncSetAttribute(k_proj, cudaFuncAttributeMaxDynamicSharedMemorySize, K1_SMEM);
    cudaFuncSetAttribute(k_out,  cudaFuncAttributeMaxDynamicSharedMemorySize, K3_SMEM);

    dim3 g1(NT / 64, 2);
    k_proj<<<g1, 256, K1_SMEM>>>(q, k, P);
    dim3 g2(SPLIT, BH);
    k_ctx<<<g2, 256>>>(v);
    k_red<<<4096 + 64, 256>>>();
    k_out<<<NT / 64, 256, K3_SMEM>>>(out);
}